// round 14
// baseline (speedup 1.0000x reference)
#include <cuda_runtime.h>
#include <cuda_fp16.h>
#include <math.h>

#define BB 8
#define TT 512
#define DD 768
#define HH 12
#define DHH 64
#define FF 3072
#define LL 12
#define BT (BB*TT)      // 4096
#define ZZ (BB*HH)      // 96

// ---------------- scratch (device globals; no allocation) ----------------
__device__ float g_hbase[BT*DD];
__device__ float g_p[BT*2];
__device__ float g_s[BT];
__device__ float g_h[BT*DD];
__device__ float g_q[BT*DD];
__device__ float g_k[BT*DD];
__device__ float g_v[BT*DD];
__device__ float g_ctx[BT*DD];
__device__ float g_attnout[BT*DD];
__device__ float g_hmid[BT*DD];
__device__ float g_ffn1[(size_t)BT*FF];
__device__ float g_ffn2[BT*DD];

__device__ __forceinline__ float f2tf(float x) {
    unsigned r;
    asm("cvt.rna.tf32.f32 %0, %1;" : "=r"(r) : "f"(x));
    return __uint_as_float(r);
}

__device__ __forceinline__ unsigned f2h2(float x, float y) {
    __half2 h = __halves2half2(__float2half_rn(x), __float2half_rn(y));
    return *(unsigned*)&h;
}

__device__ __forceinline__ unsigned su32(const void* p) {
    unsigned a;
    asm("{ .reg .u64 t; cvta.to.shared.u64 t, %1; cvt.u32.u64 %0, t; }"
        : "=r"(a) : "l"(p));
    return a;
}

__device__ __forceinline__ void mma8(float* c, unsigned a0, unsigned a1,
                                     unsigned a2, unsigned a3,
                                     unsigned b0, unsigned b1) {
    asm volatile(
        "mma.sync.aligned.m16n8k8.row.col.f32.tf32.tf32.f32 "
        "{%0,%1,%2,%3},{%4,%5,%6,%7},{%8,%9},{%0,%1,%2,%3};"
        : "+f"(c[0]), "+f"(c[1]), "+f"(c[2]), "+f"(c[3])
        : "r"(a0), "r"(a1), "r"(a2), "r"(a3), "r"(b0), "r"(b1));
}

__device__ __forceinline__ void mma16h(float* c, unsigned a0, unsigned a1,
                                       unsigned a2, unsigned a3,
                                       unsigned b0, unsigned b1) {
    asm volatile(
        "mma.sync.aligned.m16n8k16.row.col.f32.f16.f16.f32 "
        "{%0,%1,%2,%3},{%4,%5,%6,%7},{%8,%9},{%0,%1,%2,%3};"
        : "+f"(c[0]), "+f"(c[1]), "+f"(c[2]), "+f"(c[3])
        : "r"(a0), "r"(a1), "r"(a2), "r"(a3), "r"(b0), "r"(b1));
}

#define LDM_X4(r0, r1, r2, r3, addr) \
    asm volatile("ldmatrix.sync.aligned.m8n8.x4.shared.b16 {%0,%1,%2,%3}, [%4];" \
        : "=r"(r0), "=r"(r1), "=r"(r2), "=r"(r3) : "r"(addr))

// =============== fp16 tensor-core NT GEMM (ldmatrix, high occupancy) ===============
// C[M,N] = A[M,K] @ B[N,K]^T. CTA tile 128x64, warp tile 64x32 (2x2 warps, 128 thr),
// BK=16. acc=64 regs -> ~145 regs/thread -> 3 CTAs (12 warps) per SM.
// Rows of 40 halves (80B): ldmatrix row-addresses land on distinct banks.
// FUSE3: blockIdx.z selects (Bg,Cg)/(B1g,C1g)/(B2g,C2g) [QKV].
#define HROW 40
template<bool FUSE3>
__global__ void __launch_bounds__(128, 3) hgemm_nt(
    const float* __restrict__ Ag, const float* __restrict__ Bg,
    const float* __restrict__ B1g, const float* __restrict__ B2g,
    const float* __restrict__ bias, float* __restrict__ Cg,
    float* __restrict__ C1g, float* __restrict__ C2g,
    int K, int lda, int ldb, int ldc, int act)
{
    constexpr int BM = 128, BN = 64, BK = 16;
    constexpr int MI = 4, NI = 4;               // 64x32 warp tile

    __shared__ __align__(16) __half As[2][BM*HROW];
    __shared__ __align__(16) __half Bs[2][BN*HROW];

    const int z = blockIdx.z;
    const float* B; float* C;
    if constexpr (FUSE3) {
        B = (z == 0) ? Bg : (z == 1) ? B1g : B2g;
        C = (z == 0) ? Cg : (z == 1) ? C1g : C2g;
    } else { B = Bg; C = Cg; }

    const int m0 = blockIdx.y * BM;
    const int n0 = blockIdx.x * BN;
    const int tid = threadIdx.x;
    const int warp = tid >> 5, lane = tid & 31;
    const int wm = warp & 1, wn = warp >> 1;
    const int g = lane >> 2, tig = lane & 3;

    // ldmatrix per-thread source offsets (in halves)
    const int grp = lane >> 3, within = lane & 7;
    const int aoff = (within + (grp & 1)*8)*HROW + (grp >> 1)*8;
    const int boff = (within + (grp >> 1)*8)*HROW + (grp & 1)*8;
    const unsigned sbA = su32(&As[0][0]);
    const unsigned sbB = su32(&Bs[0][0]);

    // staging: 4 threads/row x 4 floats; A: 4 passes of 32 rows; B: 2 passes
    const int ar = tid >> 2;
    const int ak = (tid & 3) * 4;
    float4 pa[4], pb[2];

    auto fetchA = [&](int k0) {
#pragma unroll
        for (int i = 0; i < 4; i++)
            pa[i] = *(const float4*)(Ag + (size_t)(m0 + ar + i*32)*lda + k0 + ak);
    };
    auto fetchB = [&](int k0) {
#pragma unroll
        for (int i = 0; i < 2; i++)
            pb[i] = *(const float4*)(B + (size_t)(n0 + ar + i*32)*ldb + k0 + ak);
    };
    auto stage = [&](int buf) {
#pragma unroll
        for (int i = 0; i < 4; i++) {
            uint2 va = make_uint2(f2h2(pa[i].x, pa[i].y), f2h2(pa[i].z, pa[i].w));
            *(uint2*)&As[buf][(ar + i*32)*HROW + ak] = va;
        }
#pragma unroll
        for (int i = 0; i < 2; i++) {
            uint2 vb = make_uint2(f2h2(pb[i].x, pb[i].y), f2h2(pb[i].z, pb[i].w));
            *(uint2*)&Bs[buf][(ar + i*32)*HROW + ak] = vb;
        }
    };

    float acc[MI][NI][4];
#pragma unroll
    for (int mi = 0; mi < MI; mi++)
#pragma unroll
        for (int ni = 0; ni < NI; ni++)
#pragma unroll
            for (int r = 0; r < 4; r++) acc[mi][ni][r] = 0.f;

    auto compute = [&](int buf) {
        unsigned af[MI][4];
#pragma unroll
        for (int mi = 0; mi < MI; mi++) {
            unsigned addr = sbA + (unsigned)(buf*BM*HROW + (wm*64 + mi*16)*HROW + aoff)*2u;
            LDM_X4(af[mi][0], af[mi][1], af[mi][2], af[mi][3], addr);
        }
        unsigned bf[NI][2];
#pragma unroll
        for (int ni = 0; ni < NI; ni += 2) {
            unsigned addr = sbB + (unsigned)(buf*BN*HROW + (wn*32 + ni*8)*HROW + boff)*2u;
            LDM_X4(bf[ni][0], bf[ni][1], bf[ni+1][0], bf[ni+1][1], addr);
        }
#pragma unroll
        for (int mi = 0; mi < MI; mi++)
#pragma unroll
            for (int ni = 0; ni < NI; ni++)
                mma16h(acc[mi][ni], af[mi][0], af[mi][1], af[mi][2], af[mi][3],
                       bf[ni][0], bf[ni][1]);
    };

    fetchA(0); fetchB(0);
    stage(0);
    __syncthreads();
    int buf = 0;
    const int nk = K / BK;
    for (int it = 1; it < nk; it++) {
        fetchA(it*BK); fetchB(it*BK);
        compute(buf);
        stage(buf ^ 1);
        __syncthreads();
        buf ^= 1;
    }
    compute(buf);

    // epilogue
#pragma unroll
    for (int mi = 0; mi < MI; mi++) {
        int row0 = m0 + wm*64 + mi*16 + g;
#pragma unroll
        for (int ni = 0; ni < NI; ni++) {
            int col = n0 + wn*32 + ni*8 + tig*2;
            float c0 = acc[mi][ni][0], c1 = acc[mi][ni][1];
            float c2 = acc[mi][ni][2], c3 = acc[mi][ni][3];
            if (bias) {
                float b0 = bias[col], b1 = bias[col+1];
                c0 += b0; c1 += b1; c2 += b0; c3 += b1;
            }
            if (act) {
                c0 = 0.5f*c0*(1.f + erff(c0*0.70710678118654752f));
                c1 = 0.5f*c1*(1.f + erff(c1*0.70710678118654752f));
                c2 = 0.5f*c2*(1.f + erff(c2*0.70710678118654752f));
                c3 = 0.5f*c3*(1.f + erff(c3*0.70710678118654752f));
            }
            *(float2*)&C[(size_t)row0*ldc + col]      = make_float2(c0, c1);
            *(float2*)&C[(size_t)(row0+8)*ldc + col]  = make_float2(c2, c3);
        }
    }
}

// =============== fused flash attention (round-9, unchanged) ===============
#define FA_SMEM_FLOATS (64*68 + 64*68 + 64*72 + 4*16*68 + 3*64)
__global__ void __launch_bounds__(128) flash_attn_kernel(
        const float* __restrict__ compat_l, const float* __restrict__ gamma_l,
        const int* __restrict__ mask)
{
    extern __shared__ float sm[];
    float* Qs  = sm;
    float* Ks  = Qs + 64*68;
    float* Vs  = Ks + 64*68;
    float* Ps  = Vs + 64*72;
    float* pj0 = Ps + 4*16*68;
    float* pj1 = pj0 + 64;
    float* cj  = pj1 + 64;

    const int z = blockIdx.y, b = z / HH, hh = z % HH;
    const int i0 = blockIdx.x * 64;
    const int tid = threadIdx.x, w = tid >> 5, lane = tid & 31;
    const int g = lane >> 2, tig = lane & 3;

    const float* qb = g_q + (size_t)b*TT*DD + hh*DHH;
    const float* kb = g_k + (size_t)b*TT*DD + hh*DHH;
    const float* vb = g_v + (size_t)b*TT*DD + hh*DHH;

    {
        int r = tid >> 4, c4 = (tid & 15) * 4;
#pragma unroll
        for (int p = 0; p < 8; p++) {
            float4 v4 = *(const float4*)(qb + (size_t)(i0 + p*8 + r)*DD + c4);
            float* d = Qs + (p*8 + r)*68 + c4;
            d[0]=f2tf(v4.x); d[1]=f2tf(v4.y); d[2]=f2tf(v4.z); d[3]=f2tf(v4.w);
        }
    }

    const int gi0 = b*TT + i0 + w*16 + g;
    const float pi00 = g_p[gi0*2],       pi01 = g_p[gi0*2+1];
    const float pi10 = g_p[(gi0+8)*2],   pi11 = g_p[(gi0+8)*2+1];
    const float C00 = compat_l[hh*4+0], C01 = compat_l[hh*4+1];
    const float C10 = compat_l[hh*4+2], C11 = compat_l[hh*4+3];
    const float cp0_0 = pi00*C00 + pi01*C10, cp1_0 = pi00*C01 + pi01*C11;
    const float cp0_1 = pi10*C00 + pi11*C10, cp1_1 = pi10*C01 + pi11*C11;
    const float gm = gamma_l[0];

    float m0 = -1e30f, m1 = -1e30f, l0 = 0.f, l1 = 0.f;
    float oacc[8][4];
#pragma unroll
    for (int ni = 0; ni < 8; ni++)
#pragma unroll
        for (int r = 0; r < 4; r++) oacc[ni][r] = 0.f;

    float* Pw = Ps + w*16*68;

    for (int jt = 0; jt < 8; jt++) {
        __syncthreads();
        const int j0 = jt * 64;
        {
            int r = tid >> 4, c4 = (tid & 15) * 4;
#pragma unroll
            for (int p = 0; p < 8; p++) {
                int rr = p*8 + r;
                float4 kv = *(const float4*)(kb + (size_t)(j0 + rr)*DD + c4);
                float* dk = Ks + rr*68 + c4;
                dk[0]=f2tf(kv.x); dk[1]=f2tf(kv.y); dk[2]=f2tf(kv.z); dk[3]=f2tf(kv.w);
                float4 vv = *(const float4*)(vb + (size_t)(j0 + rr)*DD + c4);
                float* dv = Vs + rr*72 + c4;
                dv[0]=f2tf(vv.x); dv[1]=f2tf(vv.y); dv[2]=f2tf(vv.z); dv[3]=f2tf(vv.w);
            }
        }
        if (tid < 64) {
            int jg = b*TT + j0 + tid;
            pj0[tid] = g_p[jg*2];
            pj1[tid] = g_p[jg*2+1];
            cj[tid]  = gm*g_s[jg] + (1.f - (float)mask[jg]) * -10000.f;
        }
        __syncthreads();

        float sacc[8][4];
#pragma unroll
        for (int ni = 0; ni < 8; ni++)
#pragma unroll
            for (int r = 0; r < 4; r++) sacc[ni][r] = 0.f;
#pragma unroll
        for (int kk = 0; kk < 64; kk += 8) {
            unsigned a0 = __float_as_uint(Qs[(w*16+g  )*68 + kk + tig    ]);
            unsigned a1 = __float_as_uint(Qs[(w*16+g+8)*68 + kk + tig    ]);
            unsigned a2 = __float_as_uint(Qs[(w*16+g  )*68 + kk + tig + 4]);
            unsigned a3 = __float_as_uint(Qs[(w*16+g+8)*68 + kk + tig + 4]);
#pragma unroll
            for (int ni = 0; ni < 8; ni++) {
                unsigned b0 = __float_as_uint(Ks[(ni*8+g)*68 + kk + tig    ]);
                unsigned b1 = __float_as_uint(Ks[(ni*8+g)*68 + kk + tig + 4]);
                mma8(sacc[ni], a0, a1, a2, a3, b0, b1);
            }
        }

        float rm0 = -1e30f, rm1 = -1e30f;
#pragma unroll
        for (int ni = 0; ni < 8; ni++) {
#pragma unroll
            for (int c = 0; c < 2; c++) {
                int jj = ni*8 + 2*tig + c;
                float bj0 = pj0[jj], bj1 = pj1[jj], bc = cj[jj];
                sacc[ni][c]   = sacc[ni][c]  *0.125f + cp0_0*bj0 + cp1_0*bj1 + bc;
                sacc[ni][2+c] = sacc[ni][2+c]*0.125f + cp0_1*bj0 + cp1_1*bj1 + bc;
                rm0 = fmaxf(rm0, sacc[ni][c]);
                rm1 = fmaxf(rm1, sacc[ni][2+c]);
            }
        }
        rm0 = fmaxf(rm0, __shfl_xor_sync(0xffffffffu, rm0, 1));
        rm0 = fmaxf(rm0, __shfl_xor_sync(0xffffffffu, rm0, 2));
        rm1 = fmaxf(rm1, __shfl_xor_sync(0xffffffffu, rm1, 1));
        rm1 = fmaxf(rm1, __shfl_xor_sync(0xffffffffu, rm1, 2));

        float mn0 = fmaxf(m0, rm0), mn1 = fmaxf(m1, rm1);
        float sc0 = expf(m0 - mn0), sc1 = expf(m1 - mn1);
        float rs0 = 0.f, rs1 = 0.f;
#pragma unroll
        for (int ni = 0; ni < 8; ni++) {
#pragma unroll
            for (int c = 0; c < 2; c++) {
                int jj = ni*8 + 2*tig + c;
                float p0v = expf(sacc[ni][c]   - mn0); rs0 += p0v;
                float p1v = expf(sacc[ni][2+c] - mn1); rs1 += p1v;
                Pw[ g     *68 + jj] = f2tf(p0v);
                Pw[(g + 8)*68 + jj] = f2tf(p1v);
            }
        }
        rs0 += __shfl_xor_sync(0xffffffffu, rs0, 1);
        rs0 += __shfl_xor_sync(0xffffffffu, rs0, 2);
        rs1 += __shfl_xor_sync(0xffffffffu, rs1, 1);
        rs1 += __shfl_xor_sync(0xffffffffu, rs1, 2);
        l0 = l0*sc0 + rs0; l1 = l1*sc1 + rs1;
        m0 = mn0; m1 = mn1;
#pragma unroll
        for (int ni = 0; ni < 8; ni++) {
            oacc[ni][0] *= sc0; oacc[ni][1] *= sc0;
            oacc[ni][2] *= sc1; oacc[ni][3] *= sc1;
        }
        __syncwarp();

#pragma unroll
        for (int kk = 0; kk < 64; kk += 8) {
            unsigned a0 = __float_as_uint(Pw[ g     *68 + kk + tig    ]);
            unsigned a1 = __float_as_uint(Pw[(g + 8)*68 + kk + tig    ]);
            unsigned a2 = __float_as_uint(Pw[ g     *68 + kk + tig + 4]);
            unsigned a3 = __float_as_uint(Pw[(g + 8)*68 + kk + tig + 4]);
#pragma unroll
            for (int ni = 0; ni < 8; ni++) {
                unsigned b0 = __float_as_uint(Vs[(kk + tig    )*72 + ni*8 + g]);
                unsigned b1 = __float_as_uint(Vs[(kk + tig + 4)*72 + ni*8 + g]);
                mma8(oacc[ni], a0, a1, a2, a3, b0, b1);
            }
        }
        __syncwarp();
    }

    float inv0 = 1.f / l0, inv1 = 1.f / l1;
    const size_t r0 = (size_t)(b*TT + i0 + w*16 + g) * DD + hh*DHH;
#pragma unroll
    for (int ni = 0; ni < 8; ni++) {
        int col = ni*8 + 2*tig;
        *(float2*)&g_ctx[r0 + col]         = make_float2(oacc[ni][0]*inv0, oacc[ni][1]*inv0);
        *(float2*)&g_ctx[r0 + 8*DD + col]  = make_float2(oacc[ni][2]*inv1, oacc[ni][3]*inv1);
    }
}

// ---------------- stage 1 kernels (unchanged) ----------------
__global__ void embed_base_kernel(const int* __restrict__ ids,
                                  const float* __restrict__ tok,
                                  const float* __restrict__ pos,
                                  const float* __restrict__ proto,
                                  const float* __restrict__ log_tau) {
    int row = blockIdx.x;
    int t = row % TT;
    int id = ids[row];
    const float* trow = tok + (size_t)id * DD;
    const float* prow = pos + (size_t)t * DD;
    float a0 = 0.f, a1 = 0.f;
    __shared__ float r0[256], r1[256];
    for (int d = threadIdx.x; d < DD; d += 256) {
        float v = trow[d] + prow[d];
        g_hbase[(size_t)row*DD + d] = v;
        a0 += v * proto[d];
        a1 += v * proto[DD + d];
    }
    r0[threadIdx.x] = a0; r1[threadIdx.x] = a1;
    __syncthreads();
    for (int s = 128; s > 0; s >>= 1) {
        if (threadIdx.x < s) {
            r0[threadIdx.x] += r0[threadIdx.x + s];
            r1[threadIdx.x] += r1[threadIdx.x + s];
        }
        __syncthreads();
    }
    if (threadIdx.x == 0) {
        float tau = fmaxf(expf(log_tau[0]), 0.25f);
        float l0 = r0[0] / tau, l1 = r1[0] / tau;
        float m = fmaxf(l0, l1);
        float e0 = expf(l0 - m), e1 = expf(l1 - m);
        float inv = 1.f / (e0 + e1);
        g_p[row*2 + 0] = e0 * inv;
        g_p[row*2 + 1] = e1 * inv;
    }
}

__global__ void switch_kernel() {
    int i = blockIdx.x * blockDim.x + threadIdx.x;
    if (i >= BT) return;
    int t = i % TT;
    float sv = 0.f;
    if (t > 0)
        sv = 1.f - (g_p[i*2]*g_p[(i-1)*2] + g_p[i*2+1]*g_p[(i-1)*2+1]);
    g_s[i] = sv;
}

__global__ void embed_ln_kernel(const float* __restrict__ lang,
                                const float* __restrict__ sw,
                                const float* __restrict__ w,
                                const float* __restrict__ b) {
    int row = blockIdx.x;
    __shared__ float xs[DD];
    __shared__ float rs[256], rq[256];
    float p0 = g_p[row*2], p1 = g_p[row*2+1], sv = g_s[row];
    float sum = 0.f, sq = 0.f;
    for (int d = threadIdx.x; d < DD; d += 256) {
        float x = g_hbase[(size_t)row*DD + d] + p0*lang[d] + p1*lang[DD+d] + sv*sw[d];
        xs[d] = x; sum += x; sq += x*x;
    }
    rs[threadIdx.x] = sum; rq[threadIdx.x] = sq;
    __syncthreads();
    for (int s = 128; s > 0; s >>= 1) {
        if (threadIdx.x < s) { rs[threadIdx.x]+=rs[threadIdx.x+s]; rq[threadIdx.x]+=rq[threadIdx.x+s]; }
        __syncthreads();
    }
    float mu = rs[0] * (1.f/DD);
    float var = rq[0] * (1.f/DD) - mu*mu;
    float rstd = rsqrtf(var + 1e-12f);
    for (int d = threadIdx.x; d < DD; d += 256)
        g_h[(size_t)row*DD + d] = (xs[d]-mu)*rstd*w[d] + b[d];
}

__global__ void ln_residual_kernel(const float* __restrict__ a,
                                   const float* __restrict__ bres,
                                   const float* __restrict__ w,
                                   const float* __restrict__ bias,
                                   float* __restrict__ out) {
    int row = blockIdx.x;
    __shared__ float xs[DD];
    __shared__ float rs[256], rq[256];
    float sum = 0.f, sq = 0.f;
    for (int d = threadIdx.x; d < DD; d += 256) {
        float x = a[(size_t)row*DD + d] + bres[(size_t)row*DD + d];
        xs[d] = x; sum += x; sq += x*x;
    }
    rs[threadIdx.x] = sum; rq[threadIdx.x] = sq;
    __syncthreads();
    for (int s = 128; s > 0; s >>= 1) {
        if (threadIdx.x < s) { rs[threadIdx.x]+=rs[threadIdx.x+s]; rq[threadIdx.x]+=rq[threadIdx.x+s]; }
        __syncthreads();
    }
    float mu = rs[0] * (1.f/DD);
    float var = rq[0] * (1.f/DD) - mu*mu;
    float rstd = rsqrtf(var + 1e-12f);
    for (int d = threadIdx.x; d < DD; d += 256)
        out[(size_t)row*DD + d] = (xs[d]-mu)*rstd*w[d] + bias[d];
}

// ---------------- host launch ----------------
extern "C" void kernel_launch(void* const* d_in, const int* in_sizes, int n_in,
                              void* d_out, int out_size) {
    const int*   ids      = (const int*)  d_in[0];
    const int*   mask     = (const int*)  d_in[1];
    const float* tok      = (const float*)d_in[2];
    const float* pos      = (const float*)d_in[3];
    const float* lang     = (const float*)d_in[4];
    const float* sw       = (const float*)d_in[5];
    const float* proto    = (const float*)d_in[6];
    const float* log_tau  = (const float*)d_in[7];
    const float* eln_w    = (const float*)d_in[8];
    const float* eln_b    = (const float*)d_in[9];
    const float* Wq       = (const float*)d_in[10];
    const float* Wk       = (const float*)d_in[11];
    const float* Wv       = (const float*)d_in[12];
    const float* Wo       = (const float*)d_in[13];
    const float* Wob      = (const float*)d_in[14];
    const float* compat   = (const float*)d_in[15];
    const float* gamma    = (const float*)d_in[16];
    const float* W1       = (const float*)d_in[17];
    const float* b1       = (const float*)d_in[18];
    const float* W2       = (const float*)d_in[19];
    const float* b2       = (const float*)d_in[20];
    const float* ln1w     = (const float*)d_in[21];
    const float* ln1b     = (const float*)d_in[22];
    const float* ln2w     = (const float*)d_in[23];
    const float* ln2b     = (const float*)d_in[24];
    float* out = (float*)d_out;

    float *h, *q, *k, *v, *ctx, *attnout, *hmid, *ffn1, *ffn2;
    cudaGetSymbolAddress((void**)&h,       g_h);
    cudaGetSymbolAddress((void**)&q,       g_q);
    cudaGetSymbolAddress((void**)&k,       g_k);
    cudaGetSymbolAddress((void**)&v,       g_v);
    cudaGetSymbolAddress((void**)&ctx,     g_ctx);
    cudaGetSymbolAddress((void**)&attnout, g_attnout);
    cudaGetSymbolAddress((void**)&hmid,    g_hmid);
    cudaGetSymbolAddress((void**)&ffn1,    g_ffn1);
    cudaGetSymbolAddress((void**)&ffn2,    g_ffn2);

    const int fa_smem = FA_SMEM_FLOATS * 4;
    cudaFuncSetAttribute(flash_attn_kernel,
                         cudaFuncAttributeMaxDynamicSharedMemorySize, fa_smem);

    embed_base_kernel<<<BT, 256>>>(ids, tok, pos, proto, log_tau);
    switch_kernel<<<(BT + 255)/256, 256>>>();
    embed_ln_kernel<<<BT, 256>>>(lang, sw, eln_w, eln_b);

    const dim3 gQKV(DD/64, BT/128, 3);          // 12 x 32 x 3 = 1152
    const dim3 gDense(DD/64, BT/128, 1);        // 12 x 32 = 384
    const dim3 gFfn1(FF/64, BT/128, 1);         // 48 x 32 = 1536
    const dim3 gFlash(TT/64, ZZ);               // 8 x 96

    for (int l = 0; l < LL; l++) {
        const size_t wdd = (size_t)l * DD * DD;
        // fused QKV (fp16 tensor cores + ldmatrix, 128x64 tiles)
        hgemm_nt<true><<<gQKV, 128>>>(h, Wq + wdd, Wk + wdd, Wv + wdd,
            nullptr, q, k, v, DD, DD, DD, DD, 0);

        // fused attention (tf32)
        flash_attn_kernel<<<gFlash, 128, fa_smem>>>(
            compat + (size_t)l*HH*4, gamma + l, mask);

        // Wo
        hgemm_nt<false><<<gDense, 128>>>(ctx, Wo + wdd, nullptr, nullptr,
            Wob + (size_t)l*DD, attnout, nullptr, nullptr, DD, DD, DD, DD, 0);
        ln_residual_kernel<<<BT, 256>>>(h, attnout, ln1w + (size_t)l*DD, ln1b + (size_t)l*DD, hmid);

        // FFN
        hgemm_nt<false><<<gFfn1, 128>>>(hmid, W1 + (size_t)l*FF*DD, nullptr, nullptr,
            b1 + (size_t)l*FF, ffn1, nullptr, nullptr, DD, DD, DD, FF, 1);
        hgemm_nt<false><<<gDense, 128>>>(ffn1, W2 + (size_t)l*DD*FF, nullptr, nullptr,
            b2 + (size_t)l*DD, ffn2, nullptr, nullptr, FF, FF, FF, DD, 0);

        float* hout = (l == LL-1) ? out : h;
        ln_residual_kernel<<<BT, 256>>>(hmid, ffn2, ln2w + (size_t)l*DD, ln2b + (size_t)l*DD, hout);
    }
}

// round 15
// speedup vs baseline: 1.1018x; 1.1018x over previous
#include <cuda_runtime.h>
#include <cuda_fp16.h>
#include <math.h>

#define BB 8
#define TT 512
#define DD 768
#define HH 12
#define DHH 64
#define FF 3072
#define LL 12
#define BT (BB*TT)      // 4096
#define ZZ (BB*HH)      // 96

// ---------------- scratch (device globals; no allocation) ----------------
__device__ float g_hbase[BT*DD];
__device__ float g_p[BT*2];
__device__ float g_s[BT];
__device__ float g_h[BT*DD];
__device__ float g_q[BT*DD];
__device__ float g_k[BT*DD];
__device__ float g_v[BT*DD];
__device__ float g_attnout[BT*DD];
__device__ float g_hmid[BT*DD];
__device__ float g_ffn2[BT*DD];
// fp16 shadows / weights
__device__ __half g_h16[BT*DD];
__device__ __half g_ctx16[BT*DD];
__device__ __half g_hmid16[BT*DD];
__device__ __half g_ffn116[(size_t)BT*FF];
__device__ __half g_wq16[(size_t)LL*DD*DD];
__device__ __half g_wk16[(size_t)LL*DD*DD];
__device__ __half g_wv16[(size_t)LL*DD*DD];
__device__ __half g_wo16[(size_t)LL*DD*DD];
__device__ __half g_w116[(size_t)LL*FF*DD];
__device__ __half g_w216[(size_t)LL*FF*DD];

__device__ __forceinline__ float f2tf(float x) {
    unsigned r;
    asm("cvt.rna.tf32.f32 %0, %1;" : "=r"(r) : "f"(x));
    return __uint_as_float(r);
}

__device__ __forceinline__ __half2 f2h2v(float x, float y) {
    return __halves2half2(__float2half_rn(x), __float2half_rn(y));
}

__device__ __forceinline__ unsigned su32(const void* p) {
    unsigned a;
    asm("{ .reg .u64 t; cvta.to.shared.u64 t, %1; cvt.u32.u64 %0, t; }"
        : "=r"(a) : "l"(p));
    return a;
}

__device__ __forceinline__ void mma8(float* c, unsigned a0, unsigned a1,
                                     unsigned a2, unsigned a3,
                                     unsigned b0, unsigned b1) {
    asm volatile(
        "mma.sync.aligned.m16n8k8.row.col.f32.tf32.tf32.f32 "
        "{%0,%1,%2,%3},{%4,%5,%6,%7},{%8,%9},{%0,%1,%2,%3};"
        : "+f"(c[0]), "+f"(c[1]), "+f"(c[2]), "+f"(c[3])
        : "r"(a0), "r"(a1), "r"(a2), "r"(a3), "r"(b0), "r"(b1));
}

__device__ __forceinline__ void mma16h(float* c, unsigned a0, unsigned a1,
                                       unsigned a2, unsigned a3,
                                       unsigned b0, unsigned b1) {
    asm volatile(
        "mma.sync.aligned.m16n8k16.row.col.f32.f16.f16.f32 "
        "{%0,%1,%2,%3},{%4,%5,%6,%7},{%8,%9},{%0,%1,%2,%3};"
        : "+f"(c[0]), "+f"(c[1]), "+f"(c[2]), "+f"(c[3])
        : "r"(a0), "r"(a1), "r"(a2), "r"(a3), "r"(b0), "r"(b1));
}

#define LDM_X4(r0, r1, r2, r3, addr) \
    asm volatile("ldmatrix.sync.aligned.m8n8.x4.shared.b16 {%0,%1,%2,%3}, [%4];" \
        : "=r"(r0), "=r"(r1), "=r"(r2), "=r"(r3) : "r"(addr))

// ---------------- f32 -> f16 conversion (weights, once per launch) ----------------
__global__ void cvt16_kernel(const float* __restrict__ s, __half* __restrict__ d, int n) {
    int i = (blockIdx.x * 256 + threadIdx.x) * 4;
    if (i >= n) return;
    float4 v = *(const float4*)(s + i);
    *(__half2*)&d[i]     = f2h2v(v.x, v.y);
    *(__half2*)&d[i + 2] = f2h2v(v.z, v.w);
}

// =============== fp16 tensor-core NT GEMM (fp16 gmem operands, ldmatrix) ===============
// C[M,N] = A[M,K] @ B[N,K]^T, A/B fp16 row-major in gmem. CTA 128x128, warp 64x64.
// Optional f32 C and/or fp16 C16 outputs.
// FUSE3: blockIdx.z selects (Bg,Cg)/(B1g,C1g)/(B2g,C2g) [QKV].
#define HROW 40
template<bool FUSE3>
__global__ void __launch_bounds__(128) hgemm_nt(
    const __half* __restrict__ Ag, const __half* __restrict__ Bg,
    const __half* __restrict__ B1g, const __half* __restrict__ B2g,
    const float* __restrict__ bias, float* __restrict__ Cg,
    float* __restrict__ C1g, float* __restrict__ C2g, __half* __restrict__ C16,
    int K, int lda, int ldb, int ldc, int act)
{
    constexpr int BM = 128, BN = 128, BK = 16;
    constexpr int MI = 4, NI = 8;               // 64x64 warp tile

    __shared__ __align__(16) __half As[2][BM*HROW];
    __shared__ __align__(16) __half Bs[2][BN*HROW];

    const int z = blockIdx.z;
    const __half* B; float* C;
    if constexpr (FUSE3) {
        B = (z == 0) ? Bg : (z == 1) ? B1g : B2g;
        C = (z == 0) ? Cg : (z == 1) ? C1g : C2g;
    } else { B = Bg; C = Cg; }

    const int m0 = blockIdx.y * BM;
    const int n0 = blockIdx.x * BN;
    const int tid = threadIdx.x;
    const int warp = tid >> 5, lane = tid & 31;
    const int wm = warp & 1, wn = warp >> 1;
    const int g = lane >> 2, tig = lane & 3;

    // ldmatrix per-thread source offsets (in halves)
    const int grp = lane >> 3, within = lane & 7;
    const int aoff = (within + (grp & 1)*8)*HROW + (grp >> 1)*8;
    const int boff = (within + (grp >> 1)*8)*HROW + (grp & 1)*8;
    const unsigned sbA = su32(&As[0][0]);
    const unsigned sbB = su32(&Bs[0][0]);

    // staging: 2 threads/row x 8 halves (16B), 64 rows/pass, 2 passes
    const int ar = tid >> 1;
    const int ak = (tid & 1) * 8;
    uint4 pa[2], pb[2];

    auto fetchA = [&](int k0) {
#pragma unroll
        for (int i = 0; i < 2; i++)
            pa[i] = *(const uint4*)(Ag + (size_t)(m0 + ar + i*64)*lda + k0 + ak);
    };
    auto fetchB = [&](int k0) {
#pragma unroll
        for (int i = 0; i < 2; i++)
            pb[i] = *(const uint4*)(B + (size_t)(n0 + ar + i*64)*ldb + k0 + ak);
    };
    auto stage = [&](int buf) {
#pragma unroll
        for (int i = 0; i < 2; i++) {
            *(uint4*)&As[buf][(ar + i*64)*HROW + ak] = pa[i];
            *(uint4*)&Bs[buf][(ar + i*64)*HROW + ak] = pb[i];
        }
    };

    float acc[MI][NI][4];
#pragma unroll
    for (int mi = 0; mi < MI; mi++)
#pragma unroll
        for (int ni = 0; ni < NI; ni++)
#pragma unroll
            for (int r = 0; r < 4; r++) acc[mi][ni][r] = 0.f;

    auto compute = [&](int buf) {
        unsigned af[MI][4];
#pragma unroll
        for (int mi = 0; mi < MI; mi++) {
            unsigned addr = sbA + (unsigned)(buf*BM*HROW + (wm*64 + mi*16)*HROW + aoff)*2u;
            LDM_X4(af[mi][0], af[mi][1], af[mi][2], af[mi][3], addr);
        }
        unsigned bf[NI][2];
#pragma unroll
        for (int ni = 0; ni < NI; ni += 2) {
            unsigned addr = sbB + (unsigned)(buf*BN*HROW + (wn*64 + ni*8)*HROW + boff)*2u;
            LDM_X4(bf[ni][0], bf[ni][1], bf[ni+1][0], bf[ni+1][1], addr);
        }
#pragma unroll
        for (int mi = 0; mi < MI; mi++)
#pragma unroll
            for (int ni = 0; ni < NI; ni++)
                mma16h(acc[mi][ni], af[mi][0], af[mi][1], af[mi][2], af[mi][3],
                       bf[ni][0], bf[ni][1]);
    };

    fetchA(0); fetchB(0);
    stage(0);
    __syncthreads();
    int buf = 0;
    const int nk = K / BK;
    for (int it = 1; it < nk; it++) {
        fetchA(it*BK); fetchB(it*BK);
        compute(buf);
        stage(buf ^ 1);
        __syncthreads();
        buf ^= 1;
    }
    compute(buf);

    // epilogue
#pragma unroll
    for (int mi = 0; mi < MI; mi++) {
        int row0 = m0 + wm*64 + mi*16 + g;
#pragma unroll
        for (int ni = 0; ni < NI; ni++) {
            int col = n0 + wn*64 + ni*8 + tig*2;
            float c0 = acc[mi][ni][0], c1 = acc[mi][ni][1];
            float c2 = acc[mi][ni][2], c3 = acc[mi][ni][3];
            if (bias) {
                float b0 = bias[col], b1 = bias[col+1];
                c0 += b0; c1 += b1; c2 += b0; c3 += b1;
            }
            if (act) {
                c0 = 0.5f*c0*(1.f + erff(c0*0.70710678118654752f));
                c1 = 0.5f*c1*(1.f + erff(c1*0.70710678118654752f));
                c2 = 0.5f*c2*(1.f + erff(c2*0.70710678118654752f));
                c3 = 0.5f*c3*(1.f + erff(c3*0.70710678118654752f));
            }
            if (C) {
                *(float2*)&C[(size_t)row0*ldc + col]      = make_float2(c0, c1);
                *(float2*)&C[(size_t)(row0+8)*ldc + col]  = make_float2(c2, c3);
            }
            if (C16) {
                *(__half2*)&C16[(size_t)row0*ldc + col]      = f2h2v(c0, c1);
                *(__half2*)&C16[(size_t)(row0+8)*ldc + col]  = f2h2v(c2, c3);
            }
        }
    }
}

// =============== fused flash attention (writes fp16 ctx) ===============
#define FA_SMEM_FLOATS (64*68 + 64*68 + 64*72 + 4*16*68 + 3*64)
__global__ void __launch_bounds__(128) flash_attn_kernel(
        const float* __restrict__ compat_l, const float* __restrict__ gamma_l,
        const int* __restrict__ mask)
{
    extern __shared__ float sm[];
    float* Qs  = sm;
    float* Ks  = Qs + 64*68;
    float* Vs  = Ks + 64*68;
    float* Ps  = Vs + 64*72;
    float* pj0 = Ps + 4*16*68;
    float* pj1 = pj0 + 64;
    float* cj  = pj1 + 64;

    const int z = blockIdx.y, b = z / HH, hh = z % HH;
    const int i0 = blockIdx.x * 64;
    const int tid = threadIdx.x, w = tid >> 5, lane = tid & 31;
    const int g = lane >> 2, tig = lane & 3;

    const float* qb = g_q + (size_t)b*TT*DD + hh*DHH;
    const float* kb = g_k + (size_t)b*TT*DD + hh*DHH;
    const float* vb = g_v + (size_t)b*TT*DD + hh*DHH;

    {
        int r = tid >> 4, c4 = (tid & 15) * 4;
#pragma unroll
        for (int p = 0; p < 8; p++) {
            float4 v4 = *(const float4*)(qb + (size_t)(i0 + p*8 + r)*DD + c4);
            float* d = Qs + (p*8 + r)*68 + c4;
            d[0]=f2tf(v4.x); d[1]=f2tf(v4.y); d[2]=f2tf(v4.z); d[3]=f2tf(v4.w);
        }
    }

    const int gi0 = b*TT + i0 + w*16 + g;
    const float pi00 = g_p[gi0*2],       pi01 = g_p[gi0*2+1];
    const float pi10 = g_p[(gi0+8)*2],   pi11 = g_p[(gi0+8)*2+1];
    const float C00 = compat_l[hh*4+0], C01 = compat_l[hh*4+1];
    const float C10 = compat_l[hh*4+2], C11 = compat_l[hh*4+3];
    const float cp0_0 = pi00*C00 + pi01*C10, cp1_0 = pi00*C01 + pi01*C11;
    const float cp0_1 = pi10*C00 + pi11*C10, cp1_1 = pi10*C01 + pi11*C11;
    const float gm = gamma_l[0];

    float m0 = -1e30f, m1 = -1e30f, l0 = 0.f, l1 = 0.f;
    float oacc[8][4];
#pragma unroll
    for (int ni = 0; ni < 8; ni++)
#pragma unroll
        for (int r = 0; r < 4; r++) oacc[ni][r] = 0.f;

    float* Pw = Ps + w*16*68;

    for (int jt = 0; jt < 8; jt++) {
        __syncthreads();
        const int j0 = jt * 64;
        {
            int r = tid >> 4, c4 = (tid & 15) * 4;
#pragma unroll
            for (int p = 0; p < 8; p++) {
                int rr = p*8 + r;
                float4 kv = *(const float4*)(kb + (size_t)(j0 + rr)*DD + c4);
                float* dk = Ks + rr*68 + c4;
                dk[0]=f2tf(kv.x); dk[1]=f2tf(kv.y); dk[2]=f2tf(kv.z); dk[3]=f2tf(kv.w);
                float4 vv = *(const float4*)(vb + (size_t)(j0 + rr)*DD + c4);
                float* dv = Vs + rr*72 + c4;
                dv[0]=f2tf(vv.x); dv[1]=f2tf(vv.y); dv[2]=f2tf(vv.z); dv[3]=f2tf(vv.w);
            }
        }
        if (tid < 64) {
            int jg = b*TT + j0 + tid;
            pj0[tid] = g_p[jg*2];
            pj1[tid] = g_p[jg*2+1];
            cj[tid]  = gm*g_s[jg] + (1.f - (float)mask[jg]) * -10000.f;
        }
        __syncthreads();

        float sacc[8][4];
#pragma unroll
        for (int ni = 0; ni < 8; ni++)
#pragma unroll
            for (int r = 0; r < 4; r++) sacc[ni][r] = 0.f;
#pragma unroll
        for (int kk = 0; kk < 64; kk += 8) {
            unsigned a0 = __float_as_uint(Qs[(w*16+g  )*68 + kk + tig    ]);
            unsigned a1 = __float_as_uint(Qs[(w*16+g+8)*68 + kk + tig    ]);
            unsigned a2 = __float_as_uint(Qs[(w*16+g  )*68 + kk + tig + 4]);
            unsigned a3 = __float_as_uint(Qs[(w*16+g+8)*68 + kk + tig + 4]);
#pragma unroll
            for (int ni = 0; ni < 8; ni++) {
                unsigned b0 = __float_as_uint(Ks[(ni*8+g)*68 + kk + tig    ]);
                unsigned b1 = __float_as_uint(Ks[(ni*8+g)*68 + kk + tig + 4]);
                mma8(sacc[ni], a0, a1, a2, a3, b0, b1);
            }
        }

        float rm0 = -1e30f, rm1 = -1e30f;
#pragma unroll
        for (int ni = 0; ni < 8; ni++) {
#pragma unroll
            for (int c = 0; c < 2; c++) {
                int jj = ni*8 + 2*tig + c;
                float bj0 = pj0[jj], bj1 = pj1[jj], bc = cj[jj];
                sacc[ni][c]   = sacc[ni][c]  *0.125f + cp0_0*bj0 + cp1_0*bj1 + bc;
                sacc[ni][2+c] = sacc[ni][2+c]*0.125f + cp0_1*bj0 + cp1_1*bj1 + bc;
                rm0 = fmaxf(rm0, sacc[ni][c]);
                rm1 = fmaxf(rm1, sacc[ni][2+c]);
            }
        }
        rm0 = fmaxf(rm0, __shfl_xor_sync(0xffffffffu, rm0, 1));
        rm0 = fmaxf(rm0, __shfl_xor_sync(0xffffffffu, rm0, 2));
        rm1 = fmaxf(rm1, __shfl_xor_sync(0xffffffffu, rm1, 1));
        rm1 = fmaxf(rm1, __shfl_xor_sync(0xffffffffu, rm1, 2));

        float mn0 = fmaxf(m0, rm0), mn1 = fmaxf(m1, rm1);
        float sc0 = expf(m0 - mn0), sc1 = expf(m1 - mn1);
        float rs0 = 0.f, rs1 = 0.f;
#pragma unroll
        for (int ni = 0; ni < 8; ni++) {
#pragma unroll
            for (int c = 0; c < 2; c++) {
                int jj = ni*8 + 2*tig + c;
                float p0v = expf(sacc[ni][c]   - mn0); rs0 += p0v;
                float p1v = expf(sacc[ni][2+c] - mn1); rs1 += p1v;
                Pw[ g     *68 + jj] = f2tf(p0v);
                Pw[(g + 8)*68 + jj] = f2tf(p1v);
            }
        }
        rs0 += __shfl_xor_sync(0xffffffffu, rs0, 1);
        rs0 += __shfl_xor_sync(0xffffffffu, rs0, 2);
        rs1 += __shfl_xor_sync(0xffffffffu, rs1, 1);
        rs1 += __shfl_xor_sync(0xffffffffu, rs1, 2);
        l0 = l0*sc0 + rs0; l1 = l1*sc1 + rs1;
        m0 = mn0; m1 = mn1;
#pragma unroll
        for (int ni = 0; ni < 8; ni++) {
            oacc[ni][0] *= sc0; oacc[ni][1] *= sc0;
            oacc[ni][2] *= sc1; oacc[ni][3] *= sc1;
        }
        __syncwarp();

#pragma unroll
        for (int kk = 0; kk < 64; kk += 8) {
            unsigned a0 = __float_as_uint(Pw[ g     *68 + kk + tig    ]);
            unsigned a1 = __float_as_uint(Pw[(g + 8)*68 + kk + tig    ]);
            unsigned a2 = __float_as_uint(Pw[ g     *68 + kk + tig + 4]);
            unsigned a3 = __float_as_uint(Pw[(g + 8)*68 + kk + tig + 4]);
#pragma unroll
            for (int ni = 0; ni < 8; ni++) {
                unsigned b0 = __float_as_uint(Vs[(kk + tig    )*72 + ni*8 + g]);
                unsigned b1 = __float_as_uint(Vs[(kk + tig + 4)*72 + ni*8 + g]);
                mma8(oacc[ni], a0, a1, a2, a3, b0, b1);
            }
        }
        __syncwarp();
    }

    float inv0 = 1.f / l0, inv1 = 1.f / l1;
    const size_t r0 = (size_t)(b*TT + i0 + w*16 + g) * DD + hh*DHH;
#pragma unroll
    for (int ni = 0; ni < 8; ni++) {
        int col = ni*8 + 2*tig;
        *(__half2*)&g_ctx16[r0 + col]        = f2h2v(oacc[ni][0]*inv0, oacc[ni][1]*inv0);
        *(__half2*)&g_ctx16[r0 + 8*DD + col] = f2h2v(oacc[ni][2]*inv1, oacc[ni][3]*inv1);
    }
}

// ---------------- stage 1 kernels ----------------
__global__ void embed_base_kernel(const int* __restrict__ ids,
                                  const float* __restrict__ tok,
                                  const float* __restrict__ pos,
                                  const float* __restrict__ proto,
                                  const float* __restrict__ log_tau) {
    int row = blockIdx.x;
    int t = row % TT;
    int id = ids[row];
    const float* trow = tok + (size_t)id * DD;
    const float* prow = pos + (size_t)t * DD;
    float a0 = 0.f, a1 = 0.f;
    __shared__ float r0[256], r1[256];
    for (int d = threadIdx.x; d < DD; d += 256) {
        float v = trow[d] + prow[d];
        g_hbase[(size_t)row*DD + d] = v;
        a0 += v * proto[d];
        a1 += v * proto[DD + d];
    }
    r0[threadIdx.x] = a0; r1[threadIdx.x] = a1;
    __syncthreads();
    for (int s = 128; s > 0; s >>= 1) {
        if (threadIdx.x < s) {
            r0[threadIdx.x] += r0[threadIdx.x + s];
            r1[threadIdx.x] += r1[threadIdx.x + s];
        }
        __syncthreads();
    }
    if (threadIdx.x == 0) {
        float tau = fmaxf(expf(log_tau[0]), 0.25f);
        float l0 = r0[0] / tau, l1 = r1[0] / tau;
        float m = fmaxf(l0, l1);
        float e0 = expf(l0 - m), e1 = expf(l1 - m);
        float inv = 1.f / (e0 + e1);
        g_p[row*2 + 0] = e0 * inv;
        g_p[row*2 + 1] = e1 * inv;
    }
}

__global__ void switch_kernel() {
    int i = blockIdx.x * blockDim.x + threadIdx.x;
    if (i >= BT) return;
    int t = i % TT;
    float sv = 0.f;
    if (t > 0)
        sv = 1.f - (g_p[i*2]*g_p[(i-1)*2] + g_p[i*2+1]*g_p[(i-1)*2+1]);
    g_s[i] = sv;
}

__global__ void embed_ln_kernel(const float* __restrict__ lang,
                                const float* __restrict__ sw,
                                const float* __restrict__ w,
                                const float* __restrict__ b) {
    int row = blockIdx.x;
    __shared__ float xs[DD];
    __shared__ float rs[256], rq[256];
    float p0 = g_p[row*2], p1 = g_p[row*2+1], sv = g_s[row];
    float sum = 0.f, sq = 0.f;
    for (int d = threadIdx.x; d < DD; d += 256) {
        float x = g_hbase[(size_t)row*DD + d] + p0*lang[d] + p1*lang[DD+d] + sv*sw[d];
        xs[d] = x; sum += x; sq += x*x;
    }
    rs[threadIdx.x] = sum; rq[threadIdx.x] = sq;
    __syncthreads();
    for (int s = 128; s > 0; s >>= 1) {
        if (threadIdx.x < s) { rs[threadIdx.x]+=rs[threadIdx.x+s]; rq[threadIdx.x]+=rq[threadIdx.x+s]; }
        __syncthreads();
    }
    float mu = rs[0] * (1.f/DD);
    float var = rq[0] * (1.f/DD) - mu*mu;
    float rstd = rsqrtf(var + 1e-12f);
    for (int d = threadIdx.x; d < DD; d += 256) {
        float v = (xs[d]-mu)*rstd*w[d] + b[d];
        g_h[(size_t)row*DD + d] = v;
        g_h16[(size_t)row*DD + d] = __float2half_rn(v);
    }
}

__global__ void ln_residual_kernel(const float* __restrict__ a,
                                   const float* __restrict__ bres,
                                   const float* __restrict__ w,
                                   const float* __restrict__ bias,
                                   float* __restrict__ out,
                                   __half* __restrict__ out16) {
    int row = blockIdx.x;
    __shared__ float xs[DD];
    __shared__ float rs[256], rq[256];
    float sum = 0.f, sq = 0.f;
    for (int d = threadIdx.x; d < DD; d += 256) {
        float x = a[(size_t)row*DD + d] + bres[(size_t)row*DD + d];
        xs[d] = x; sum += x; sq += x*x;
    }
    rs[threadIdx.x] = sum; rq[threadIdx.x] = sq;
    __syncthreads();
    for (int s = 128; s > 0; s >>= 1) {
        if (threadIdx.x < s) { rs[threadIdx.x]+=rs[threadIdx.x+s]; rq[threadIdx.x]+=rq[threadIdx.x+s]; }
        __syncthreads();
    }
    float mu = rs[0] * (1.f/DD);
    float var = rq[0] * (1.f/DD) - mu*mu;
    float rstd = rsqrtf(var + 1e-12f);
    for (int d = threadIdx.x; d < DD; d += 256) {
        float v = (xs[d]-mu)*rstd*w[d] + bias[d];
        out[(size_t)row*DD + d] = v;
        if (out16) out16[(size_t)row*DD + d] = __float2half_rn(v);
    }
}

// ---------------- host launch ----------------
extern "C" void kernel_launch(void* const* d_in, const int* in_sizes, int n_in,
                              void* d_out, int out_size) {
    const int*   ids      = (const int*)  d_in[0];
    const int*   mask     = (const int*)  d_in[1];
    const float* tok      = (const float*)d_in[2];
    const float* pos      = (const float*)d_in[3];
    const float* lang     = (const float*)d_in[4];
    const float* sw       = (const float*)d_in[5];
    const float* proto    = (const float*)d_in[6];
    const float* log_tau  = (const float*)d_in[7];
    const float* eln_w    = (const float*)d_in[8];
    const float* eln_b    = (const float*)d_in[9];
    const float* Wq       = (const float*)d_in[10];
    const float* Wk       = (const float*)d_in[11];
    const float* Wv       = (const float*)d_in[12];
    const float* Wo       = (const float*)d_in[13];
    const float* Wob      = (const float*)d_in[14];
    const float* compat   = (const float*)d_in[15];
    const float* gamma    = (const float*)d_in[16];
    const float* W1       = (const float*)d_in[17];
    const float* b1       = (const float*)d_in[18];
    const float* W2       = (const float*)d_in[19];
    const float* b2       = (const float*)d_in[20];
    const float* ln1w     = (const float*)d_in[21];
    const float* ln1b     = (const float*)d_in[22];
    const float* ln2w     = (const float*)d_in[23];
    const float* ln2b     = (const float*)d_in[24];
    float* out = (float*)d_out;

    float *h, *q, *k, *v, *attnout, *hmid, *ffn2;
    __half *h16, *ctx16, *hmid16, *ffn116;
    __half *wq16, *wk16, *wv16, *wo16, *w116, *w216;
    cudaGetSymbolAddress((void**)&h,       g_h);
    cudaGetSymbolAddress((void**)&q,       g_q);
    cudaGetSymbolAddress((void**)&k,       g_k);
    cudaGetSymbolAddress((void**)&v,       g_v);
    cudaGetSymbolAddress((void**)&attnout, g_attnout);
    cudaGetSymbolAddress((void**)&hmid,    g_hmid);
    cudaGetSymbolAddress((void**)&ffn2,    g_ffn2);
    cudaGetSymbolAddress((void**)&h16,     g_h16);
    cudaGetSymbolAddress((void**)&ctx16,   g_ctx16);
    cudaGetSymbolAddress((void**)&hmid16,  g_hmid16);
    cudaGetSymbolAddress((void**)&ffn116,  g_ffn116);
    cudaGetSymbolAddress((void**)&wq16,    g_wq16);
    cudaGetSymbolAddress((void**)&wk16,    g_wk16);
    cudaGetSymbolAddress((void**)&wv16,    g_wv16);
    cudaGetSymbolAddress((void**)&wo16,    g_wo16);
    cudaGetSymbolAddress((void**)&w116,    g_w116);
    cudaGetSymbolAddress((void**)&w216,    g_w216);

    const int fa_smem = FA_SMEM_FLOATS * 4;
    cudaFuncSetAttribute(flash_attn_kernel,
                         cudaFuncAttributeMaxDynamicSharedMemorySize, fa_smem);

    // weight conversion (once per launch)
    const int nDD = LL*DD*DD, nFD = LL*FF*DD;
    cvt16_kernel<<<nDD/1024, 256>>>(Wq, wq16, nDD);
    cvt16_kernel<<<nDD/1024, 256>>>(Wk, wk16, nDD);
    cvt16_kernel<<<nDD/1024, 256>>>(Wv, wv16, nDD);
    cvt16_kernel<<<nDD/1024, 256>>>(Wo, wo16, nDD);
    cvt16_kernel<<<nFD/1024, 256>>>(W1, w116, nFD);
    cvt16_kernel<<<nFD/1024, 256>>>(W2, w216, nFD);

    embed_base_kernel<<<BT, 256>>>(ids, tok, pos, proto, log_tau);
    switch_kernel<<<(BT + 255)/256, 256>>>();
    embed_ln_kernel<<<BT, 256>>>(lang, sw, eln_w, eln_b);

    const dim3 gQKV(DD/128, BT/128, 3);         // 576
    const dim3 gDense(DD/128, BT/128, 1);       // 192
    const dim3 gFfn1(FF/128, BT/128, 1);        // 768
    const dim3 gFlash(TT/64, ZZ);               // 8 x 96

    for (int l = 0; l < LL; l++) {
        const size_t wdd = (size_t)l * DD * DD;
        const size_t wfd = (size_t)l * FF * DD;
        // fused QKV
        hgemm_nt<true><<<gQKV, 128>>>(h16, wq16 + wdd, wk16 + wdd, wv16 + wdd,
            nullptr, q, k, v, nullptr, DD, DD, DD, DD, 0);

        // fused attention (tf32) -> ctx16
        flash_attn_kernel<<<gFlash, 128, fa_smem>>>(
            compat + (size_t)l*HH*4, gamma + l, mask);

        // Wo
        hgemm_nt<false><<<gDense, 128>>>(ctx16, wo16 + wdd, nullptr, nullptr,
            Wob + (size_t)l*DD, attnout, nullptr, nullptr, nullptr, DD, DD, DD, DD, 0);
        ln_residual_kernel<<<BT, 256>>>(h, attnout, ln1w + (size_t)l*DD, ln1b + (size_t)l*DD,
                                        hmid, hmid16);

        // FFN1 (gelu, fp16-only output)
        hgemm_nt<false><<<gFfn1, 128>>>(hmid16, w116 + wfd, nullptr, nullptr,
            b1 + (size_t)l*FF, nullptr, nullptr, nullptr, ffn116, DD, DD, DD, FF, 1);
        // FFN2
        hgemm_nt<false><<<gDense, 128>>>(ffn116, w216 + wfd, nullptr, nullptr,
            b2 + (size_t)l*DD, ffn2, nullptr, nullptr, nullptr, FF, FF, FF, DD, 0);

        float* hout = (l == LL-1) ? out : h;
        ln_residual_kernel<<<BT, 256>>>(hmid, ffn2, ln2w + (size_t)l*DD, ln2b + (size_t)l*DD,
                                        hout, h16);
    }
}

// round 16
// speedup vs baseline: 1.2058x; 1.0944x over previous
#include <cuda_runtime.h>
#include <cuda_fp16.h>
#include <math.h>

#define BB 8
#define TT 512
#define DD 768
#define HH 12
#define DHH 64
#define FF 3072
#define LL 12
#define BT (BB*TT)      // 4096
#define ZZ (BB*HH)      // 96

// ---------------- scratch (device globals; no allocation) ----------------
__device__ float g_hbase[BT*DD];
__device__ float g_p[BT*2];
__device__ float g_s[BT];
__device__ float g_h[BT*DD];
__device__ float g_attnout[BT*DD];
__device__ float g_hmid[BT*DD];
__device__ float g_ffn2[BT*DD];
// fp16 buffers
__device__ __half g_h16[BT*DD];
__device__ __half g_q16[BT*DD];
__device__ __half g_k16[BT*DD];
__device__ __half g_v16[BT*DD];
__device__ __half g_ctx16[BT*DD];
__device__ __half g_hmid16[BT*DD];
__device__ __half g_ffn116[(size_t)BT*FF];
__device__ __half g_wq16[(size_t)LL*DD*DD];
__device__ __half g_wk16[(size_t)LL*DD*DD];
__device__ __half g_wv16[(size_t)LL*DD*DD];
__device__ __half g_wo16[(size_t)LL*DD*DD];
__device__ __half g_w116[(size_t)LL*FF*DD];
__device__ __half g_w216[(size_t)LL*FF*DD];

__device__ __forceinline__ __half2 f2h2v(float x, float y) {
    return __halves2half2(__float2half_rn(x), __float2half_rn(y));
}

__device__ __forceinline__ unsigned su32(const void* p) {
    unsigned a;
    asm("{ .reg .u64 t; cvta.to.shared.u64 t, %1; cvt.u32.u64 %0, t; }"
        : "=r"(a) : "l"(p));
    return a;
}

__device__ __forceinline__ void mma16h(float* c, unsigned a0, unsigned a1,
                                       unsigned a2, unsigned a3,
                                       unsigned b0, unsigned b1) {
    asm volatile(
        "mma.sync.aligned.m16n8k16.row.col.f32.f16.f16.f32 "
        "{%0,%1,%2,%3},{%4,%5,%6,%7},{%8,%9},{%0,%1,%2,%3};"
        : "+f"(c[0]), "+f"(c[1]), "+f"(c[2]), "+f"(c[3])
        : "r"(a0), "r"(a1), "r"(a2), "r"(a3), "r"(b0), "r"(b1));
}

#define LDM_X4(r0, r1, r2, r3, addr) \
    asm volatile("ldmatrix.sync.aligned.m8n8.x4.shared.b16 {%0,%1,%2,%3}, [%4];" \
        : "=r"(r0), "=r"(r1), "=r"(r2), "=r"(r3) : "r"(addr))

#define LDM_X4_T(r0, r1, r2, r3, addr) \
    asm volatile("ldmatrix.sync.aligned.m8n8.x4.trans.shared.b16 {%0,%1,%2,%3}, [%4];" \
        : "=r"(r0), "=r"(r1), "=r"(r2), "=r"(r3) : "r"(addr))

// ---------------- f32 -> f16 conversion (weights, once per launch) ----------------
__global__ void cvt16_kernel(const float* __restrict__ s, __half* __restrict__ d, int n) {
    int i = (blockIdx.x * 256 + threadIdx.x) * 4;
    if (i >= n) return;
    float4 v = *(const float4*)(s + i);
    *(__half2*)&d[i]     = f2h2v(v.x, v.y);
    *(__half2*)&d[i + 2] = f2h2v(v.z, v.w);
}

// =============== fp16 tensor-core NT GEMM (fp16 gmem operands, ldmatrix) ===============
// C[M,N] = A[M,K] @ B[N,K]^T. CTA 128x128, warp 64x64 (2x2 warps, 128 thr), BK=16.
// Outputs: optional f32 Cf, optional fp16 (C16/C116/C216; FUSE3 selects by z).
#define HROW 40
template<bool FUSE3>
__global__ void __launch_bounds__(128) hgemm_nt(
    const __half* __restrict__ Ag, const __half* __restrict__ Bg,
    const __half* __restrict__ B1g, const __half* __restrict__ B2g,
    const float* __restrict__ bias, float* __restrict__ Cf,
    __half* __restrict__ C16, __half* __restrict__ C116, __half* __restrict__ C216,
    int K, int lda, int ldb, int ldc, int act)
{
    constexpr int BM = 128, BN = 128, BK = 16;
    constexpr int MI = 4, NI = 8;

    __shared__ __align__(16) __half As[2][BM*HROW];
    __shared__ __align__(16) __half Bs[2][BN*HROW];

    const int z = blockIdx.z;
    const __half* B; __half* Ch;
    if constexpr (FUSE3) {
        B  = (z == 0) ? Bg  : (z == 1) ? B1g  : B2g;
        Ch = (z == 0) ? C16 : (z == 1) ? C116 : C216;
    } else { B = Bg; Ch = C16; }

    const int m0 = blockIdx.y * BM;
    const int n0 = blockIdx.x * BN;
    const int tid = threadIdx.x;
    const int warp = tid >> 5, lane = tid & 31;
    const int wm = warp & 1, wn = warp >> 1;
    const int g = lane >> 2, tig = lane & 3;

    const int grp = lane >> 3, within = lane & 7;
    const int aoff = (within + (grp & 1)*8)*HROW + (grp >> 1)*8;
    const int boff = (within + (grp >> 1)*8)*HROW + (grp & 1)*8;
    const unsigned sbA = su32(&As[0][0]);
    const unsigned sbB = su32(&Bs[0][0]);

    const int ar = tid >> 1;
    const int ak = (tid & 1) * 8;
    uint4 pa[2], pb[2];

    auto fetchA = [&](int k0) {
#pragma unroll
        for (int i = 0; i < 2; i++)
            pa[i] = *(const uint4*)(Ag + (size_t)(m0 + ar + i*64)*lda + k0 + ak);
    };
    auto fetchB = [&](int k0) {
#pragma unroll
        for (int i = 0; i < 2; i++)
            pb[i] = *(const uint4*)(B + (size_t)(n0 + ar + i*64)*ldb + k0 + ak);
    };
    auto stage = [&](int buf) {
#pragma unroll
        for (int i = 0; i < 2; i++) {
            *(uint4*)&As[buf][(ar + i*64)*HROW + ak] = pa[i];
            *(uint4*)&Bs[buf][(ar + i*64)*HROW + ak] = pb[i];
        }
    };

    float acc[MI][NI][4];
#pragma unroll
    for (int mi = 0; mi < MI; mi++)
#pragma unroll
        for (int ni = 0; ni < NI; ni++)
#pragma unroll
            for (int r = 0; r < 4; r++) acc[mi][ni][r] = 0.f;

    auto compute = [&](int buf) {
        unsigned af[MI][4];
#pragma unroll
        for (int mi = 0; mi < MI; mi++) {
            unsigned addr = sbA + (unsigned)(buf*BM*HROW + (wm*64 + mi*16)*HROW + aoff)*2u;
            LDM_X4(af[mi][0], af[mi][1], af[mi][2], af[mi][3], addr);
        }
        unsigned bf[NI][2];
#pragma unroll
        for (int ni = 0; ni < NI; ni += 2) {
            unsigned addr = sbB + (unsigned)(buf*BN*HROW + (wn*64 + ni*8)*HROW + boff)*2u;
            LDM_X4(bf[ni][0], bf[ni][1], bf[ni+1][0], bf[ni+1][1], addr);
        }
#pragma unroll
        for (int mi = 0; mi < MI; mi++)
#pragma unroll
            for (int ni = 0; ni < NI; ni++)
                mma16h(acc[mi][ni], af[mi][0], af[mi][1], af[mi][2], af[mi][3],
                       bf[ni][0], bf[ni][1]);
    };

    fetchA(0); fetchB(0);
    stage(0);
    __syncthreads();
    int buf = 0;
    const int nk = K / BK;
    for (int it = 1; it < nk; it++) {
        fetchA(it*BK); fetchB(it*BK);
        compute(buf);
        stage(buf ^ 1);
        __syncthreads();
        buf ^= 1;
    }
    compute(buf);

#pragma unroll
    for (int mi = 0; mi < MI; mi++) {
        int row0 = m0 + wm*64 + mi*16 + g;
#pragma unroll
        for (int ni = 0; ni < NI; ni++) {
            int col = n0 + wn*64 + ni*8 + tig*2;
            float c0 = acc[mi][ni][0], c1 = acc[mi][ni][1];
            float c2 = acc[mi][ni][2], c3 = acc[mi][ni][3];
            if (bias) {
                float b0 = bias[col], b1 = bias[col+1];
                c0 += b0; c1 += b1; c2 += b0; c3 += b1;
            }
            if (act) {
                c0 = 0.5f*c0*(1.f + erff(c0*0.70710678118654752f));
                c1 = 0.5f*c1*(1.f + erff(c1*0.70710678118654752f));
                c2 = 0.5f*c2*(1.f + erff(c2*0.70710678118654752f));
                c3 = 0.5f*c3*(1.f + erff(c3*0.70710678118654752f));
            }
            if (Cf) {
                *(float2*)&Cf[(size_t)row0*ldc + col]      = make_float2(c0, c1);
                *(float2*)&Cf[(size_t)(row0+8)*ldc + col]  = make_float2(c2, c3);
            }
            if (Ch) {
                *(__half2*)&Ch[(size_t)row0*ldc + col]      = f2h2v(c0, c1);
                *(__half2*)&Ch[(size_t)(row0+8)*ldc + col]  = f2h2v(c2, c3);
            }
        }
    }
}

// =============== fused flash attention (fp16 tensor cores) ===============
// grid (TT/64, ZZ), 128 thr (4 warps x 16 q-rows). Q/K/V fp16 in gmem.
#define VROW 72
__global__ void __launch_bounds__(128) flash_attn_kernel(
        const float* __restrict__ compat_l, const float* __restrict__ gamma_l,
        const int* __restrict__ mask)
{
    __shared__ __align__(16) __half Qs[64*VROW];
    __shared__ __align__(16) __half Ks[64*VROW];
    __shared__ __align__(16) __half Vs[64*VROW];
    __shared__ __align__(16) __half Ps[4][16*VROW];
    __shared__ float pj0[64], pj1[64], cj[64];

    const int z = blockIdx.y, b = z / HH, hh = z % HH;
    const int i0 = blockIdx.x * 64;
    const int tid = threadIdx.x, w = tid >> 5, lane = tid & 31;
    const int g = lane >> 2, tig = lane & 3;
    const int grp = lane >> 3, within = lane & 7;
    const int moff = (within + (grp & 1)*8)*VROW + (grp >> 1)*8;   // A / trans-B pattern
    const int boff = (within + (grp >> 1)*8)*VROW + (grp & 1)*8;   // NT-B pattern

    const unsigned sbQ = su32(Qs), sbK = su32(Ks), sbV = su32(Vs);
    const unsigned sbP = su32(&Ps[w][0]);

    const __half* qb = g_q16 + (size_t)(b*TT)*DD + hh*DHH;
    const __half* kb = g_k16 + (size_t)(b*TT)*DD + hh*DHH;
    const __half* vb = g_v16 + (size_t)(b*TT)*DD + hh*DHH;

    // load Q tile (fp16 direct)
    const int lr = tid >> 3, lc = (tid & 7)*8;
#pragma unroll
    for (int p = 0; p < 4; p++) {
        int row = p*16 + lr;
        *(uint4*)&Qs[row*VROW + lc] = *(const uint4*)(qb + (size_t)(i0+row)*DD + lc);
    }
    __syncthreads();

    // hoist Q fragments (invariant across j-tiles)
    unsigned aq[4][4];
#pragma unroll
    for (int kbk = 0; kbk < 4; kbk++) {
        unsigned addr = sbQ + (unsigned)((w*16)*VROW + kbk*16 + moff)*2u;
        LDM_X4(aq[kbk][0], aq[kbk][1], aq[kbk][2], aq[kbk][3], addr);
    }

    const int gi0 = b*TT + i0 + w*16 + g;
    const float pi00 = g_p[gi0*2],       pi01 = g_p[gi0*2+1];
    const float pi10 = g_p[(gi0+8)*2],   pi11 = g_p[(gi0+8)*2+1];
    const float C00 = compat_l[hh*4+0], C01 = compat_l[hh*4+1];
    const float C10 = compat_l[hh*4+2], C11 = compat_l[hh*4+3];
    const float cp0_0 = pi00*C00 + pi01*C10, cp1_0 = pi00*C01 + pi01*C11;
    const float cp0_1 = pi10*C00 + pi11*C10, cp1_1 = pi10*C01 + pi11*C11;
    const float gm = gamma_l[0];

    float m0 = -1e30f, m1 = -1e30f, l0 = 0.f, l1 = 0.f;
    float oacc[8][4];
#pragma unroll
    for (int ni = 0; ni < 8; ni++)
#pragma unroll
        for (int r = 0; r < 4; r++) oacc[ni][r] = 0.f;

    __half* Pw = &Ps[w][0];

    for (int jt = 0; jt < 8; jt++) {
        __syncthreads();                 // previous PV reads of Vs / Ks done
        const int j0 = jt * 64;
#pragma unroll
        for (int p = 0; p < 4; p++) {
            int row = p*16 + lr;
            *(uint4*)&Ks[row*VROW + lc] = *(const uint4*)(kb + (size_t)(j0+row)*DD + lc);
            *(uint4*)&Vs[row*VROW + lc] = *(const uint4*)(vb + (size_t)(j0+row)*DD + lc);
        }
        if (tid < 64) {
            int jg = b*TT + j0 + tid;
            pj0[tid] = g_p[jg*2];
            pj1[tid] = g_p[jg*2+1];
            cj[tid]  = gm*g_s[jg] + (1.f - (float)mask[jg]) * -10000.f;
        }
        __syncthreads();

        // S = Q @ K^T  (fp16 mma)
        float sacc[8][4];
#pragma unroll
        for (int ni = 0; ni < 8; ni++)
#pragma unroll
            for (int r = 0; r < 4; r++) sacc[ni][r] = 0.f;
#pragma unroll
        for (int kbk = 0; kbk < 4; kbk++) {
            unsigned bf[8][2];
#pragma unroll
            for (int ni = 0; ni < 8; ni += 2) {
                unsigned addr = sbK + (unsigned)((ni*8)*VROW + kbk*16 + boff)*2u;
                LDM_X4(bf[ni][0], bf[ni][1], bf[ni+1][0], bf[ni+1][1], addr);
            }
#pragma unroll
            for (int ni = 0; ni < 8; ni++)
                mma16h(sacc[ni], aq[kbk][0], aq[kbk][1], aq[kbk][2], aq[kbk][3],
                       bf[ni][0], bf[ni][1]);
        }

        // bias + row max
        float rm0 = -1e30f, rm1 = -1e30f;
#pragma unroll
        for (int ni = 0; ni < 8; ni++) {
#pragma unroll
            for (int c = 0; c < 2; c++) {
                int jj = ni*8 + 2*tig + c;
                float bj0 = pj0[jj], bj1 = pj1[jj], bc = cj[jj];
                sacc[ni][c]   = sacc[ni][c]  *0.125f + cp0_0*bj0 + cp1_0*bj1 + bc;
                sacc[ni][2+c] = sacc[ni][2+c]*0.125f + cp0_1*bj0 + cp1_1*bj1 + bc;
                rm0 = fmaxf(rm0, sacc[ni][c]);
                rm1 = fmaxf(rm1, sacc[ni][2+c]);
            }
        }
        rm0 = fmaxf(rm0, __shfl_xor_sync(0xffffffffu, rm0, 1));
        rm0 = fmaxf(rm0, __shfl_xor_sync(0xffffffffu, rm0, 2));
        rm1 = fmaxf(rm1, __shfl_xor_sync(0xffffffffu, rm1, 1));
        rm1 = fmaxf(rm1, __shfl_xor_sync(0xffffffffu, rm1, 2));

        float mn0 = fmaxf(m0, rm0), mn1 = fmaxf(m1, rm1);
        float sc0 = expf(m0 - mn0), sc1 = expf(m1 - mn1);
        float rs0 = 0.f, rs1 = 0.f;
#pragma unroll
        for (int ni = 0; ni < 8; ni++) {
            int jj = ni*8 + 2*tig;
            float p00 = expf(sacc[ni][0] - mn0);
            float p01 = expf(sacc[ni][1] - mn0);
            float p10 = expf(sacc[ni][2] - mn1);
            float p11 = expf(sacc[ni][3] - mn1);
            rs0 += p00 + p01; rs1 += p10 + p11;
            *(__half2*)&Pw[ g     *VROW + jj] = f2h2v(p00, p01);
            *(__half2*)&Pw[(g + 8)*VROW + jj] = f2h2v(p10, p11);
        }
        rs0 += __shfl_xor_sync(0xffffffffu, rs0, 1);
        rs0 += __shfl_xor_sync(0xffffffffu, rs0, 2);
        rs1 += __shfl_xor_sync(0xffffffffu, rs1, 1);
        rs1 += __shfl_xor_sync(0xffffffffu, rs1, 2);
        l0 = l0*sc0 + rs0; l1 = l1*sc1 + rs1;
        m0 = mn0; m1 = mn1;
#pragma unroll
        for (int ni = 0; ni < 8; ni++) {
            oacc[ni][0] *= sc0; oacc[ni][1] *= sc0;
            oacc[ni][2] *= sc1; oacc[ni][3] *= sc1;
        }
        __syncwarp();

        // O += P @ V   (A = P via ldmatrix, B = V^T via ldmatrix.trans)
#pragma unroll
        for (int kbk = 0; kbk < 4; kbk++) {
            unsigned ap[4];
            LDM_X4(ap[0], ap[1], ap[2], ap[3],
                   sbP + (unsigned)(kbk*16 + moff)*2u);
            unsigned bv[8][2];
#pragma unroll
            for (int ni = 0; ni < 8; ni += 2) {
                unsigned addr = sbV + (unsigned)((kbk*16)*VROW + ni*8 + moff)*2u;
                LDM_X4_T(bv[ni][0], bv[ni][1], bv[ni+1][0], bv[ni+1][1], addr);
            }
#pragma unroll
            for (int ni = 0; ni < 8; ni++)
                mma16h(oacc[ni], ap[0], ap[1], ap[2], ap[3], bv[ni][0], bv[ni][1]);
        }
        __syncwarp();
    }

    float inv0 = 1.f / l0, inv1 = 1.f / l1;
    const size_t r0 = (size_t)(b*TT + i0 + w*16 + g) * DD + hh*DHH;
#pragma unroll
    for (int ni = 0; ni < 8; ni++) {
        int col = ni*8 + 2*tig;
        *(__half2*)&g_ctx16[r0 + col]        = f2h2v(oacc[ni][0]*inv0, oacc[ni][1]*inv0);
        *(__half2*)&g_ctx16[r0 + 8*DD + col] = f2h2v(oacc[ni][2]*inv1, oacc[ni][3]*inv1);
    }
}

// ---------------- stage 1 kernels ----------------
__global__ void embed_base_kernel(const int* __restrict__ ids,
                                  const float* __restrict__ tok,
                                  const float* __restrict__ pos,
                                  const float* __restrict__ proto,
                                  const float* __restrict__ log_tau) {
    int row = blockIdx.x;
    int t = row % TT;
    int id = ids[row];
    const float* trow = tok + (size_t)id * DD;
    const float* prow = pos + (size_t)t * DD;
    float a0 = 0.f, a1 = 0.f;
    __shared__ float r0[256], r1[256];
    for (int d = threadIdx.x; d < DD; d += 256) {
        float v = trow[d] + prow[d];
        g_hbase[(size_t)row*DD + d] = v;
        a0 += v * proto[d];
        a1 += v * proto[DD + d];
    }
    r0[threadIdx.x] = a0; r1[threadIdx.x] = a1;
    __syncthreads();
    for (int s = 128; s > 0; s >>= 1) {
        if (threadIdx.x < s) {
            r0[threadIdx.x] += r0[threadIdx.x + s];
            r1[threadIdx.x] += r1[threadIdx.x + s];
        }
        __syncthreads();
    }
    if (threadIdx.x == 0) {
        float tau = fmaxf(expf(log_tau[0]), 0.25f);
        float l0 = r0[0] / tau, l1 = r1[0] / tau;
        float m = fmaxf(l0, l1);
        float e0 = expf(l0 - m), e1 = expf(l1 - m);
        float inv = 1.f / (e0 + e1);
        g_p[row*2 + 0] = e0 * inv;
        g_p[row*2 + 1] = e1 * inv;
    }
}

__global__ void switch_kernel() {
    int i = blockIdx.x * blockDim.x + threadIdx.x;
    if (i >= BT) return;
    int t = i % TT;
    float sv = 0.f;
    if (t > 0)
        sv = 1.f - (g_p[i*2]*g_p[(i-1)*2] + g_p[i*2+1]*g_p[(i-1)*2+1]);
    g_s[i] = sv;
}

__global__ void embed_ln_kernel(const float* __restrict__ lang,
                                const float* __restrict__ sw,
                                const float* __restrict__ w,
                                const float* __restrict__ b) {
    int row = blockIdx.x;
    __shared__ float xs[DD];
    __shared__ float rs[256], rq[256];
    float p0 = g_p[row*2], p1 = g_p[row*2+1], sv = g_s[row];
    float sum = 0.f, sq = 0.f;
    for (int d = threadIdx.x; d < DD; d += 256) {
        float x = g_hbase[(size_t)row*DD + d] + p0*lang[d] + p1*lang[DD+d] + sv*sw[d];
        xs[d] = x; sum += x; sq += x*x;
    }
    rs[threadIdx.x] = sum; rq[threadIdx.x] = sq;
    __syncthreads();
    for (int s = 128; s > 0; s >>= 1) {
        if (threadIdx.x < s) { rs[threadIdx.x]+=rs[threadIdx.x+s]; rq[threadIdx.x]+=rq[threadIdx.x+s]; }
        __syncthreads();
    }
    float mu = rs[0] * (1.f/DD);
    float var = rq[0] * (1.f/DD) - mu*mu;
    float rstd = rsqrtf(var + 1e-12f);
    for (int d = threadIdx.x; d < DD; d += 256) {
        float v = (xs[d]-mu)*rstd*w[d] + b[d];
        g_h[(size_t)row*DD + d] = v;
        g_h16[(size_t)row*DD + d] = __float2half_rn(v);
    }
}

__global__ void ln_residual_kernel(const float* __restrict__ a,
                                   const float* __restrict__ bres,
                                   const float* __restrict__ w,
                                   const float* __restrict__ bias,
                                   float* __restrict__ out,
                                   __half* __restrict__ out16) {
    int row = blockIdx.x;
    __shared__ float xs[DD];
    __shared__ float rs[256], rq[256];
    float sum = 0.f, sq = 0.f;
    for (int d = threadIdx.x; d < DD; d += 256) {
        float x = a[(size_t)row*DD + d] + bres[(size_t)row*DD + d];
        xs[d] = x; sum += x; sq += x*x;
    }
    rs[threadIdx.x] = sum; rq[threadIdx.x] = sq;
    __syncthreads();
    for (int s = 128; s > 0; s >>= 1) {
        if (threadIdx.x < s) { rs[threadIdx.x]+=rs[threadIdx.x+s]; rq[threadIdx.x]+=rq[threadIdx.x+s]; }
        __syncthreads();
    }
    float mu = rs[0] * (1.f/DD);
    float var = rq[0] * (1.f/DD) - mu*mu;
    float rstd = rsqrtf(var + 1e-12f);
    for (int d = threadIdx.x; d < DD; d += 256) {
        float v = (xs[d]-mu)*rstd*w[d] + bias[d];
        out[(size_t)row*DD + d] = v;
        if (out16) out16[(size_t)row*DD + d] = __float2half_rn(v);
    }
}

// ---------------- host launch ----------------
extern "C" void kernel_launch(void* const* d_in, const int* in_sizes, int n_in,
                              void* d_out, int out_size) {
    const int*   ids      = (const int*)  d_in[0];
    const int*   mask     = (const int*)  d_in[1];
    const float* tok      = (const float*)d_in[2];
    const float* pos      = (const float*)d_in[3];
    const float* lang     = (const float*)d_in[4];
    const float* sw       = (const float*)d_in[5];
    const float* proto    = (const float*)d_in[6];
    const float* log_tau  = (const float*)d_in[7];
    const float* eln_w    = (const float*)d_in[8];
    const float* eln_b    = (const float*)d_in[9];
    const float* Wq       = (const float*)d_in[10];
    const float* Wk       = (const float*)d_in[11];
    const float* Wv       = (const float*)d_in[12];
    const float* Wo       = (const float*)d_in[13];
    const float* Wob      = (const float*)d_in[14];
    const float* compat   = (const float*)d_in[15];
    const float* gamma    = (const float*)d_in[16];
    const float* W1       = (const float*)d_in[17];
    const float* b1       = (const float*)d_in[18];
    const float* W2       = (const float*)d_in[19];
    const float* b2       = (const float*)d_in[20];
    const float* ln1w     = (const float*)d_in[21];
    const float* ln1b     = (const float*)d_in[22];
    const float* ln2w     = (const float*)d_in[23];
    const float* ln2b     = (const float*)d_in[24];
    float* out = (float*)d_out;

    float *h, *attnout, *hmid, *ffn2;
    __half *h16, *q16, *k16, *v16, *ctx16, *hmid16, *ffn116;
    __half *wq16, *wk16, *wv16, *wo16, *w116, *w216;
    cudaGetSymbolAddress((void**)&h,       g_h);
    cudaGetSymbolAddress((void**)&attnout, g_attnout);
    cudaGetSymbolAddress((void**)&hmid,    g_hmid);
    cudaGetSymbolAddress((void**)&ffn2,    g_ffn2);
    cudaGetSymbolAddress((void**)&h16,     g_h16);
    cudaGetSymbolAddress((void**)&q16,     g_q16);
    cudaGetSymbolAddress((void**)&k16,     g_k16);
    cudaGetSymbolAddress((void**)&v16,     g_v16);
    cudaGetSymbolAddress((void**)&ctx16,   g_ctx16);
    cudaGetSymbolAddress((void**)&hmid16,  g_hmid16);
    cudaGetSymbolAddress((void**)&ffn116,  g_ffn116);
    cudaGetSymbolAddress((void**)&wq16,    g_wq16);
    cudaGetSymbolAddress((void**)&wk16,    g_wk16);
    cudaGetSymbolAddress((void**)&wv16,    g_wv16);
    cudaGetSymbolAddress((void**)&wo16,    g_wo16);
    cudaGetSymbolAddress((void**)&w116,    g_w116);
    cudaGetSymbolAddress((void**)&w216,    g_w216);

    // weight conversion (once per launch)
    const int nDD = LL*DD*DD, nFD = LL*FF*DD;
    cvt16_kernel<<<nDD/1024, 256>>>(Wq, wq16, nDD);
    cvt16_kernel<<<nDD/1024, 256>>>(Wk, wk16, nDD);
    cvt16_kernel<<<nDD/1024, 256>>>(Wv, wv16, nDD);
    cvt16_kernel<<<nDD/1024, 256>>>(Wo, wo16, nDD);
    cvt16_kernel<<<nFD/1024, 256>>>(W1, w116, nFD);
    cvt16_kernel<<<nFD/1024, 256>>>(W2, w216, nFD);

    embed_base_kernel<<<BT, 256>>>(ids, tok, pos, proto, log_tau);
    switch_kernel<<<(BT + 255)/256, 256>>>();
    embed_ln_kernel<<<BT, 256>>>(lang, sw, eln_w, eln_b);

    const dim3 gQKV(DD/128, BT/128, 3);         // 576
    const dim3 gDense(DD/128, BT/128, 1);       // 192
    const dim3 gFfn1(FF/128, BT/128, 1);        // 768
    const dim3 gFlash(TT/64, ZZ);               // 8 x 96

    for (int l = 0; l < LL; l++) {
        const size_t wdd = (size_t)l * DD * DD;
        const size_t wfd = (size_t)l * FF * DD;
        // fused QKV -> fp16 q/k/v
        hgemm_nt<true><<<gQKV, 128>>>(h16, wq16 + wdd, wk16 + wdd, wv16 + wdd,
            nullptr, nullptr, q16, k16, v16, DD, DD, DD, DD, 0);

        // fused attention (fp16 tensor cores) -> ctx16
        flash_attn_kernel<<<gFlash, 128>>>(
            compat + (size_t)l*HH*4, gamma + l, mask);

        // Wo -> f32 attnout
        hgemm_nt<false><<<gDense, 128>>>(ctx16, wo16 + wdd, nullptr, nullptr,
            Wob + (size_t)l*DD, attnout, nullptr, nullptr, nullptr, DD, DD, DD, DD, 0);
        ln_residual_kernel<<<BT, 256>>>(h, attnout, ln1w + (size_t)l*DD, ln1b + (size_t)l*DD,
                                        hmid, hmid16);

        // FFN1 (gelu) -> fp16 only
        hgemm_nt<false><<<gFfn1, 128>>>(hmid16, w116 + wfd, nullptr, nullptr,
            b1 + (size_t)l*FF, nullptr, ffn116, nullptr, nullptr, DD, DD, DD, FF, 1);
        // FFN2 -> f32
        hgemm_nt<false><<<gDense, 128>>>(ffn116, w216 + wfd, nullptr, nullptr,
            b2 + (size_t)l*DD, ffn2, nullptr, nullptr, nullptr, FF, FF, FF, DD, 0);

        float* hout = (l == LL-1) ? out : h;
        ln_residual_kernel<<<BT, 256>>>(hmid, ffn2, ln2w + (size_t)l*DD, ln2b + (size_t)l*DD,
                                        hout, h16);
    }
}